// round 1
// baseline (speedup 1.0000x reference)
#include <cuda_runtime.h>

// LNN_89464168776130 — fused grad + Hessian-row of 2-64-64-64-1 tanh MLP.
// Per sample: forward with tangent e_v (JVP), reverse with tangent (HVP row),
// all in fp32 using packed fma.rn.f32x2 for 2x FFMA throughput on sm_103a.
//
// Inputs (metadata order): t(int,ignored), x[B,2], W0[2,64], b0[64],
// W1[64,64], b1[64], W2[64,64], b2[64], W3[64,1], b3[1](ignored).
// Output: [B,2] = concat(v, a), a = (L_q - L_vq*v) / (L_vv + 0.1).

typedef unsigned long long u64;

#define TPB 256
#define SPB 128           // samples per block
#define ACT_STRIDE 257    // 4*64 + 1 pad word -> conflict-free lane access

// SMEM layout (float offsets)
#define OFF_W1S 0
#define OFF_W1T 4096
#define OFF_W2S 8192
#define OFF_W2T 12288
#define OFF_W0  16384     // 128 floats: W0[0][k] at k, W0[1][k] at 64+k
#define OFF_B0  16512
#define OFF_B1  16576
#define OFF_B2  16640
#define OFF_W3  16704
#define OFF_ACT 16768
#define SMEM_FLOATS (OFF_ACT + SPB * ACT_STRIDE)     // 49664
#define SMEM_BYTES  (SMEM_FLOATS * 4)                // 198656 B

// Accurate-enough cheap tanh: 1 - 2/(exp(2x)+1) via ex2/rcp approx (~1e-7 rel).
__device__ __forceinline__ float fast_tanh(float x) {
    float e;
    asm("ex2.approx.f32 %0, %1;" : "=f"(e) : "f"(x * 2.8853900817779268f));
    float r;
    asm("rcp.approx.f32 %0, %1;" : "=f"(r) : "f"(e + 1.0f));
    return fmaf(-2.0f, r, 1.0f);
}

__device__ __forceinline__ u64 pack2(float lo, float hi) {
    u64 r; asm("mov.b64 %0, {%1, %2};" : "=l"(r) : "f"(lo), "f"(hi)); return r;
}
__device__ __forceinline__ void unpack2(float &lo, float &hi, u64 p) {
    asm("mov.b64 {%0, %1}, %2;" : "=f"(lo), "=f"(hi) : "l"(p));
}
// acc += a * b (packed 2x fp32)
__device__ __forceinline__ void ffma2(u64 &acc, u64 a, u64 b) {
    asm("fma.rn.f32x2 %0, %1, %2, %0;" : "+l"(acc) : "l"(a), "l"(b));
}

__global__ __launch_bounds__(TPB, 1)
void lnn_kernel(const float* __restrict__ x,
                const float* __restrict__ W0, const float* __restrict__ b0,
                const float* __restrict__ W1, const float* __restrict__ b1,
                const float* __restrict__ W2, const float* __restrict__ b2,
                const float* __restrict__ W3,
                float* __restrict__ out, int B)
{
    extern __shared__ float sm[];
    const int t = threadIdx.x;

    // ---- cooperative weight load (+ transposes for backward matvecs) ----
    for (int i = t; i < 4096; i += TPB) {
        int k = i >> 6, j = i & 63;
        float w1 = W1[i];
        sm[OFF_W1S + i] = w1;
        sm[OFF_W1T + j * 64 + k] = w1;
        float w2 = W2[i];
        sm[OFF_W2S + i] = w2;
        sm[OFF_W2T + j * 64 + k] = w2;
    }
    if (t < 128) sm[OFF_W0 + t] = W0[t];
    if (t < 64) {
        sm[OFF_B0 + t] = b0[t];
        sm[OFF_B1 + t] = b1[t];
        sm[OFF_B2 + t] = b2[t];
        sm[OFF_W3 + t] = W3[t];
    }
    __syncthreads();

    const int s     = t & (SPB - 1);   // sample within block
    const int half  = t >> 7;          // 0/1: which 32-output half this thread owns
    const int jbase = half * 32;
    long gs = (long)blockIdx.x * SPB + s;
    const bool active = (gs < (long)B);
    if (!active) gs = 0;               // clamp for safe loads; no store later

    const float2 xv = ((const float2*)x)[gs];
    const float q = xv.x, v = xv.y;
    float* act = sm + OFF_ACT + s * ACT_STRIDE;
    // arrays within act: A=+0, B=+64, C=+128, D=+192

    // ---- F0: h0_k = tanh(q*W0[0,k] + v*W0[1,k] + b0_k), my 32 k's -> A ----
#pragma unroll
    for (int kk = 0; kk < 32; kk++) {
        int k = jbase + kk;
        float z = fmaf(q, sm[OFF_W0 + k], fmaf(v, sm[OFF_W0 + 64 + k], sm[OFF_B0 + k]));
        act[k] = fast_tanh(z);
    }
    __syncthreads();

    // ---- F1: z1 = h0@W1 + b1, zd1 = hd0@W1 ; h1->B, hd1->C ----
    // hd0_k = (1-h0_k^2) * W0[1,k] recomputed inline.
#pragma unroll
    for (int tile = 0; tile < 2; tile++) {
        const int j0 = jbase + tile * 16;
        u64 az[8], ad[8];
#pragma unroll
        for (int i = 0; i < 8; i++) {
            az[i] = pack2(sm[OFF_B1 + j0 + 2 * i], sm[OFF_B1 + j0 + 2 * i + 1]);
            ad[i] = 0ULL;
        }
#pragma unroll 8
        for (int k = 0; k < 64; k++) {
            float a   = act[k];
            float u0  = fmaf(-a, a, 1.0f);
            float hd0 = u0 * sm[OFF_W0 + 64 + k];
            u64 av = pack2(a, a);
            u64 hv = pack2(hd0, hd0);
            const float4* wr = (const float4*)(sm + OFF_W1S + k * 64 + j0);
#pragma unroll
            for (int i = 0; i < 4; i++) {
                float4 w = wr[i];
                u64 w01 = pack2(w.x, w.y), w23 = pack2(w.z, w.w);
                ffma2(az[2 * i],     w01, av);
                ffma2(az[2 * i + 1], w23, av);
                ffma2(ad[2 * i],     w01, hv);
                ffma2(ad[2 * i + 1], w23, hv);
            }
        }
#pragma unroll
        for (int i = 0; i < 8; i++) {
            float z0, z1v, zd0, zd1;
            unpack2(z0, z1v, az[i]);
            unpack2(zd0, zd1, ad[i]);
            float ha = fast_tanh(z0), hb = fast_tanh(z1v);
            int j = j0 + 2 * i;
            act[64 + j]      = ha;
            act[64 + j + 1]  = hb;
            act[128 + j]     = fmaf(-ha, ha, 1.0f) * zd0;
            act[128 + j + 1] = fmaf(-hb, hb, 1.0f) * zd1;
        }
    }
    __syncthreads();

    // ---- F2: z2 = h1@W2 + b2, zd2 = hd1@W2 ; fold to d2->A, dd2->D ----
#pragma unroll
    for (int tile = 0; tile < 2; tile++) {
        const int j0 = jbase + tile * 16;
        u64 az[8], ad[8];
#pragma unroll
        for (int i = 0; i < 8; i++) {
            az[i] = pack2(sm[OFF_B2 + j0 + 2 * i], sm[OFF_B2 + j0 + 2 * i + 1]);
            ad[i] = 0ULL;
        }
#pragma unroll 8
        for (int k = 0; k < 64; k++) {
            float hb = act[64 + k];
            float hc = act[128 + k];
            u64 av = pack2(hb, hb);
            u64 hv = pack2(hc, hc);
            const float4* wr = (const float4*)(sm + OFF_W2S + k * 64 + j0);
#pragma unroll
            for (int i = 0; i < 4; i++) {
                float4 w = wr[i];
                u64 w01 = pack2(w.x, w.y), w23 = pack2(w.z, w.w);
                ffma2(az[2 * i],     w01, av);
                ffma2(az[2 * i + 1], w23, av);
                ffma2(ad[2 * i],     w01, hv);
                ffma2(ad[2 * i + 1], w23, hv);
            }
        }
#pragma unroll
        for (int i = 0; i < 8; i++) {
            float z0, z1v, zd0, zd1;
            unpack2(z0, z1v, az[i]);
            unpack2(zd0, zd1, ad[i]);
            int j = j0 + 2 * i;
            {
                float h2v = fast_tanh(z0);
                float u2  = fmaf(-h2v, h2v, 1.0f);
                float hd2 = u2 * zd0;
                float w3v = sm[OFF_W3 + j];
                act[j]       = w3v * u2;                       // d2
                act[192 + j] = w3v * (-2.0f * h2v * hd2);      // dd2
            }
            {
                float h2v = fast_tanh(z1v);
                float u2  = fmaf(-h2v, h2v, 1.0f);
                float hd2 = u2 * zd1;
                float w3v = sm[OFF_W3 + j + 1];
                act[j + 1]       = w3v * u2;
                act[192 + j + 1] = w3v * (-2.0f * h2v * hd2);
            }
        }
    }
    __syncthreads();

    // ---- B1: g1 = d2@W2^T, gd1 = dd2@W2^T ; fold to d1->B, dd1->C ----
#pragma unroll
    for (int tile = 0; tile < 2; tile++) {
        const int k0 = jbase + tile * 16;
        u64 ag[8], agd[8];
#pragma unroll
        for (int i = 0; i < 8; i++) { ag[i] = 0ULL; agd[i] = 0ULL; }
#pragma unroll 8
        for (int j = 0; j < 64; j++) {
            float a = act[j];         // d2
            float d = act[192 + j];   // dd2
            u64 av = pack2(a, a);
            u64 dv = pack2(d, d);
            const float4* wr = (const float4*)(sm + OFF_W2T + j * 64 + k0);
#pragma unroll
            for (int i = 0; i < 4; i++) {
                float4 w = wr[i];
                u64 w01 = pack2(w.x, w.y), w23 = pack2(w.z, w.w);
                ffma2(ag[2 * i],      w01, av);
                ffma2(ag[2 * i + 1],  w23, av);
                ffma2(agd[2 * i],     w01, dv);
                ffma2(agd[2 * i + 1], w23, dv);
            }
        }
#pragma unroll
        for (int i = 0; i < 8; i++) {
            float g0v, g1v, gd0, gd1;
            unpack2(g0v, g1v, ag[i]);
            unpack2(gd0, gd1, agd[i]);
            int k = k0 + 2 * i;
            {
                float h1 = act[64 + k], hd1 = act[128 + k];
                float u1 = fmaf(-h1, h1, 1.0f);
                act[64 + k]  = g0v * u1;                                   // d1
                act[128 + k] = fmaf(gd0, u1, -2.0f * g0v * h1 * hd1);      // dd1
            }
            {
                float h1 = act[64 + k + 1], hd1 = act[128 + k + 1];
                float u1 = fmaf(-h1, h1, 1.0f);
                act[64 + k + 1]  = g1v * u1;
                act[128 + k + 1] = fmaf(gd1, u1, -2.0f * g1v * h1 * hd1);
            }
        }
    }
    __syncthreads();

    // ---- B0: g0 = d1@W1^T, gd0 = dd1@W1^T ; fold with recomputed h0,
    //      accumulate grad_q, H_qv, H_vv partials ----
    float p0 = 0.0f, p1 = 0.0f, p2 = 0.0f;
#pragma unroll
    for (int tile = 0; tile < 2; tile++) {
        const int k0 = jbase + tile * 16;
        u64 ag[8], agd[8];
#pragma unroll
        for (int i = 0; i < 8; i++) { ag[i] = 0ULL; agd[i] = 0ULL; }
#pragma unroll 8
        for (int j = 0; j < 64; j++) {
            float a = act[64 + j];    // d1
            float d = act[128 + j];   // dd1
            u64 av = pack2(a, a);
            u64 dv = pack2(d, d);
            const float4* wr = (const float4*)(sm + OFF_W1T + j * 64 + k0);
#pragma unroll
            for (int i = 0; i < 4; i++) {
                float4 w = wr[i];
                u64 w01 = pack2(w.x, w.y), w23 = pack2(w.z, w.w);
                ffma2(ag[2 * i],      w01, av);
                ffma2(ag[2 * i + 1],  w23, av);
                ffma2(agd[2 * i],     w01, dv);
                ffma2(agd[2 * i + 1], w23, dv);
            }
        }
#pragma unroll
        for (int i = 0; i < 8; i++) {
            float ga, gb, gda, gdb;
            unpack2(ga, gb, ag[i]);
            unpack2(gda, gdb, agd[i]);
#pragma unroll
            for (int e = 0; e < 2; e++) {
                int k = k0 + 2 * i + e;
                float g  = e ? gb : ga;
                float gd = e ? gdb : gda;
                float w00 = sm[OFF_W0 + k];
                float w01v = sm[OFF_W0 + 64 + k];
                float z0k = fmaf(q, w00, fmaf(v, w01v, sm[OFF_B0 + k]));
                float h0 = fast_tanh(z0k);
                float u0 = fmaf(-h0, h0, 1.0f);
                float hd0 = u0 * w01v;
                float d0  = g * u0;
                float dd0 = fmaf(gd, u0, -2.0f * g * h0 * hd0);
                p0 = fmaf(d0, w00, p0);    // grad_q partial
                p1 = fmaf(dd0, w00, p1);   // H_qv partial
                p2 = fmaf(dd0, w01v, p2);  // H_vv partial
            }
        }
    }

    // combine the two half-threads' partials via smem (A region is dead)
    if (half) { act[0] = p0; act[1] = p1; act[2] = p2; }
    __syncthreads();
    if (!half && active) {
        float gq  = p0 + act[0];
        float hqv = p1 + act[1];
        float hvv = p2 + act[2];
        float a = (gq - hqv * v) / (hvv + 0.1f);
        ((float2*)out)[gs] = make_float2(v, a);
    }
}

extern "C" void kernel_launch(void* const* d_in, const int* in_sizes, int n_in,
                              void* d_out, int out_size) {
    const float* x  = (const float*)d_in[1];
    const float* W0 = (const float*)d_in[2];
    const float* b0 = (const float*)d_in[3];
    const float* W1 = (const float*)d_in[4];
    const float* b1 = (const float*)d_in[5];
    const float* W2 = (const float*)d_in[6];
    const float* b2 = (const float*)d_in[7];
    const float* W3 = (const float*)d_in[8];
    float* out = (float*)d_out;

    const int B = in_sizes[1] / 2;   // x has B*2 elements
    const int grid = (B + SPB - 1) / SPB;

    cudaFuncSetAttribute(lnn_kernel, cudaFuncAttributeMaxDynamicSharedMemorySize,
                         SMEM_BYTES);
    lnn_kernel<<<grid, TPB, SMEM_BYTES>>>(x, W0, b0, W1, b1, W2, b2, W3, out, B);
}

// round 3
// speedup vs baseline: 2.8132x; 2.8132x over previous
#include <cuda_runtime.h>
#include <cuda_bf16.h>

typedef unsigned int u32;

#define TPB 256
#define NW  8   // warps per CTA

// SMEM: B-fragment bank (4 stages x 4 ktiles x 8 ntiles x 32 lanes x uint4)
//       = 4096 uint4 = 64 KB, then 6x64 fp32 consts.
#define SMEM_BYTES (65536 + 6 * 64 * 4)

__device__ __forceinline__ float ftanh(float x) {
    float e; asm("ex2.approx.f32 %0, %1;" : "=f"(e) : "f"(x * 2.8853900817779268f));
    float r; asm("rcp.approx.f32 %0, %1;" : "=f"(r) : "f"(e + 1.0f));
    return fmaf(-2.0f, r, 1.0f);
}

// split (a,b) -> packed bf16x2 hi + residual lo
__device__ __forceinline__ void split2(float a, float b, u32 &hi, u32 &lo) {
    __nv_bfloat162 h2 = __floats2bfloat162_rn(a, b);
    hi = *reinterpret_cast<u32*>(&h2);
    float ar = __bfloat162float(__low2bfloat16(h2));
    float br = __bfloat162float(__high2bfloat16(h2));
    __nv_bfloat162 l2 = __floats2bfloat162_rn(a - ar, b - br);
    lo = *reinterpret_cast<u32*>(&l2);
}

__device__ __forceinline__ void mma16816(float* d, const u32* a, u32 b0, u32 b1) {
    asm volatile(
        "mma.sync.aligned.m16n8k16.row.col.f32.bf16.bf16.f32 "
        "{%0,%1,%2,%3},{%4,%5,%6,%7},{%8,%9},{%0,%1,%2,%3};"
        : "+f"(d[0]), "+f"(d[1]), "+f"(d[2]), "+f"(d[3])
        : "r"(a[0]), "r"(a[1]), "r"(a[2]), "r"(a[3]), "r"(b0), "r"(b1));
}

// One GEMM stage: [16,64] x [64,64] for value (A=Ah/Al -> zacc) and
// tangent (A=Th/Tl -> dacc), 3-term bf16 split.
#define RUN_STAGE(S) do {                                                     \
    _Pragma("unroll")                                                         \
    for (int nt = 0; nt < 8; nt++) {                                          \
        _Pragma("unroll")                                                     \
        for (int j = 0; j < 4; j++) { zacc[nt][j] = 0.f; dacc[nt][j] = 0.f; } \
    }                                                                         \
    _Pragma("unroll")                                                         \
    for (int kt = 0; kt < 4; kt++) {                                          \
        _Pragma("unroll")                                                     \
        for (int nt = 0; nt < 8; nt++) {                                      \
            uint4 bf = bfr[(((S) * 4 + kt) * 8 + nt) * 32 + lane];            \
            mma16816(zacc[nt], Ah[kt], bf.x, bf.y);                           \
            mma16816(zacc[nt], Ah[kt], bf.z, bf.w);                           \
            mma16816(zacc[nt], Al[kt], bf.x, bf.y);                           \
            mma16816(dacc[nt], Th[kt], bf.x, bf.y);                           \
            mma16816(dacc[nt], Th[kt], bf.z, bf.w);                           \
            mma16816(dacc[nt], Tl[kt], bf.x, bf.y);                           \
        }                                                                     \
    }                                                                         \
} while (0)

// Convert D fragments (zacc/dacc, m16n8 layout) into next-stage A fragments
// (m16k16 layout). D of ntiles (2kt,2kt+1) == A of ktile kt, reg-for-reg.
#define PACK_AFRAGS() do {                                                    \
    _Pragma("unroll")                                                         \
    for (int kt = 0; kt < 4; kt++) {                                          \
        split2(zacc[2*kt][0],   zacc[2*kt][1],   Ah[kt][0], Al[kt][0]);       \
        split2(zacc[2*kt][2],   zacc[2*kt][3],   Ah[kt][1], Al[kt][1]);       \
        split2(zacc[2*kt+1][0], zacc[2*kt+1][1], Ah[kt][2], Al[kt][2]);       \
        split2(zacc[2*kt+1][2], zacc[2*kt+1][3], Ah[kt][3], Al[kt][3]);       \
        split2(dacc[2*kt][0],   dacc[2*kt][1],   Th[kt][0], Tl[kt][0]);       \
        split2(dacc[2*kt][2],   dacc[2*kt][3],   Th[kt][1], Tl[kt][1]);       \
        split2(dacc[2*kt+1][0], dacc[2*kt+1][1], Th[kt][2], Tl[kt][2]);       \
        split2(dacc[2*kt+1][2], dacc[2*kt+1][3], Th[kt][3], Tl[kt][3]);       \
    }                                                                         \
} while (0)

__global__ void __launch_bounds__(TPB, 1)
lnn_mma(const float2* __restrict__ X,
        const float* __restrict__ W0, const float* __restrict__ b0,
        const float* __restrict__ W1, const float* __restrict__ b1,
        const float* __restrict__ W2, const float* __restrict__ b2,
        const float* __restrict__ W3,
        float2* __restrict__ out, int B, int nchunks)
{
    extern __shared__ __align__(16) char sm[];
    uint4* bfr = (uint4*)sm;
    float* cs = (float*)(sm + 65536);
    float* w00f = cs;       float* w01f = cs + 64;
    float* b0f  = cs + 128; float* b1f  = cs + 192;
    float* b2f  = cs + 256; float* w3f  = cs + 320;

    const int t = threadIdx.x;
    if (t < 64) {
        w00f[t] = W0[t];     w01f[t] = W0[64 + t];
        b0f[t]  = b0[t];     b1f[t]  = b1[t];
        b2f[t]  = b2[t];     w3f[t]  = W3[t];
    }
    // ---- pre-pack weight B-fragments (hi/lo bf16) ----
    // stage 0: B[k,n]=W1[k,n]   (F1)
    // stage 1: B[k,n]=W2[k,n]   (F2)
    // stage 2: B[k,n]=W2[n,k]   (B1)
    // stage 3: B[k,n]=W1[n,k]   (B0)
    for (int i = t; i < 4096; i += TPB) {
        int ln = i & 31, nt = (i >> 5) & 7, kt = (i >> 8) & 3, s = i >> 10;
        int k0 = kt * 16 + (ln & 3) * 2;
        int n  = nt * 8 + (ln >> 2);
        float v0, v1, v2, v3;
        if (s == 0) {
            v0 = W1[k0*64+n]; v1 = W1[(k0+1)*64+n];
            v2 = W1[(k0+8)*64+n]; v3 = W1[(k0+9)*64+n];
        } else if (s == 1) {
            v0 = W2[k0*64+n]; v1 = W2[(k0+1)*64+n];
            v2 = W2[(k0+8)*64+n]; v3 = W2[(k0+9)*64+n];
        } else if (s == 2) {
            v0 = W2[n*64+k0]; v1 = W2[n*64+k0+1];
            v2 = W2[n*64+k0+8]; v3 = W2[n*64+k0+9];
        } else {
            v0 = W1[n*64+k0]; v1 = W1[n*64+k0+1];
            v2 = W1[n*64+k0+8]; v3 = W1[n*64+k0+9];
        }
        u32 h0, l0, h1, l1;
        split2(v0, v1, h0, l0);
        split2(v2, v3, h1, l1);
        bfr[i] = make_uint4(h0, h1, l0, l1);
    }
    __syncthreads();

    const int lane = t & 31, warp = t >> 5;
    const int qr = lane >> 2;          // row within 8-row group
    const int qc = (lane & 3) * 2;     // col pair base

    for (int chunk = blockIdx.x * NW + warp; chunk < nchunks;
         chunk += gridDim.x * NW) {
        const int r0 = chunk * 16 + qr, r1 = r0 + 8;
        float2 x0 = (r0 < B) ? X[r0] : make_float2(0.f, 0.f);
        float2 x1 = (r1 < B) ? X[r1] : make_float2(0.f, 0.f);
        const float q0 = x0.x, v0 = x0.y, q1 = x1.x, v1 = x1.y;

        u32 Ah[4][4], Al[4][4], Th[4][4], Tl[4][4];

        // ===== F0: h0 (value) and hd0 (tangent) as A fragments =====
#pragma unroll
        for (int kt = 0; kt < 4; kt++) {
#pragma unroll
            for (int hh = 0; hh < 2; hh++) {
                int k = kt * 16 + hh * 8 + qc;
                float wa = w00f[k], wb = w00f[k+1];
                float wc = w01f[k], wd = w01f[k+1];
                float ba = b0f[k],  bb = b0f[k+1];
                float z00 = fmaf(q0, wa, fmaf(v0, wc, ba));
                float z01 = fmaf(q0, wb, fmaf(v0, wd, bb));
                float z10 = fmaf(q1, wa, fmaf(v1, wc, ba));
                float z11 = fmaf(q1, wb, fmaf(v1, wd, bb));
                float h00 = ftanh(z00), h01 = ftanh(z01);
                float h10 = ftanh(z10), h11 = ftanh(z11);
                float d00 = fmaf(-h00, h00, 1.f) * wc;
                float d01 = fmaf(-h01, h01, 1.f) * wd;
                float d10 = fmaf(-h10, h10, 1.f) * wc;
                float d11 = fmaf(-h11, h11, 1.f) * wd;
                split2(h00, h01, Ah[kt][hh*2],   Al[kt][hh*2]);
                split2(h10, h11, Ah[kt][hh*2+1], Al[kt][hh*2+1]);
                split2(d00, d01, Th[kt][hh*2],   Tl[kt][hh*2]);
                split2(d10, d11, Th[kt][hh*2+1], Tl[kt][hh*2+1]);
            }
        }

        float zacc[8][4], dacc[8][4];
        RUN_STAGE(0);

        // ===== F1 elementwise: z1 -> h1,hd1 (stash in regs, D-aligned) =====
        float h1s[8][4], hd1s[8][4];
#pragma unroll
        for (int nt = 0; nt < 8; nt++) {
#pragma unroll
            for (int j = 0; j < 4; j++) {
                int col = nt * 8 + qc + (j & 1);
                float h = ftanh(zacc[nt][j] + b1f[col]);
                float u = fmaf(-h, h, 1.f);
                float hd = u * dacc[nt][j];
                h1s[nt][j] = h; hd1s[nt][j] = hd;
                zacc[nt][j] = h; dacc[nt][j] = hd;
            }
        }
        PACK_AFRAGS();
        RUN_STAGE(1);

        // ===== F2 elementwise: z2 -> d2, dd2 =====
#pragma unroll
        for (int nt = 0; nt < 8; nt++) {
#pragma unroll
            for (int j = 0; j < 4; j++) {
                int col = nt * 8 + qc + (j & 1);
                float h = ftanh(zacc[nt][j] + b2f[col]);
                float u = fmaf(-h, h, 1.f);
                float hd = u * dacc[nt][j];
                float w3v = w3f[col];
                zacc[nt][j] = w3v * u;                 // d2
                dacc[nt][j] = -2.f * w3v * h * hd;     // dd2
            }
        }
        PACK_AFRAGS();
        RUN_STAGE(2);

        // ===== B1 elementwise: g1,gd1 -> d1,dd1 (uses stashed h1,hd1) =====
#pragma unroll
        for (int nt = 0; nt < 8; nt++) {
#pragma unroll
            for (int j = 0; j < 4; j++) {
                float g = zacc[nt][j], gd = dacc[nt][j];
                float h = h1s[nt][j], hd = hd1s[nt][j];
                float u = fmaf(-h, h, 1.f);
                zacc[nt][j] = g * u;
                dacc[nt][j] = fmaf(gd, u, -2.f * g * h * hd);
            }
        }
        PACK_AFRAGS();
        RUN_STAGE(3);

        // ===== B0 fold: g0,gd0 + recomputed h0 -> per-row partials =====
        float p00 = 0.f, p01 = 0.f, p02 = 0.f;
        float p10 = 0.f, p11 = 0.f, p12 = 0.f;
#pragma unroll
        for (int nt = 0; nt < 8; nt++) {
#pragma unroll
            for (int j = 0; j < 4; j++) {
                int k = nt * 8 + qc + (j & 1);
                int rh = j >> 1;
                float q = rh ? q1 : q0, v = rh ? v1 : v0;
                float wa = w00f[k], wc = w01f[k];
                float z0 = fmaf(q, wa, fmaf(v, wc, b0f[k]));
                float h = ftanh(z0);
                float u = fmaf(-h, h, 1.f);
                float hd = u * wc;
                float g = zacc[nt][j], gd = dacc[nt][j];
                float d0 = g * u;
                float dd0 = fmaf(gd, u, -2.f * g * h * hd);
                if (rh) {
                    p10 = fmaf(d0, wa, p10);
                    p11 = fmaf(dd0, wa, p11);
                    p12 = fmaf(dd0, wc, p12);
                } else {
                    p00 = fmaf(d0, wa, p00);
                    p01 = fmaf(dd0, wa, p01);
                    p02 = fmaf(dd0, wc, p02);
                }
            }
        }
        // reduce across the 4 lanes of each quad (they hold disjoint k's)
#pragma unroll
        for (int m = 1; m <= 2; m <<= 1) {
            p00 += __shfl_xor_sync(0xFFFFFFFFu, p00, m);
            p01 += __shfl_xor_sync(0xFFFFFFFFu, p01, m);
            p02 += __shfl_xor_sync(0xFFFFFFFFu, p02, m);
            p10 += __shfl_xor_sync(0xFFFFFFFFu, p10, m);
            p11 += __shfl_xor_sync(0xFFFFFFFFu, p11, m);
            p12 += __shfl_xor_sync(0xFFFFFFFFu, p12, m);
        }
        if ((lane & 3) == 0) {
            if (r0 < B) {
                float a = (p00 - p01 * v0) / (p02 + 0.1f);
                out[r0] = make_float2(v0, a);
            }
            if (r1 < B) {
                float a = (p10 - p11 * v1) / (p12 + 0.1f);
                out[r1] = make_float2(v1, a);
            }
        }
    }
}

extern "C" void kernel_launch(void* const* d_in, const int* in_sizes, int n_in,
                              void* d_out, int out_size) {
    const float* x  = (const float*)d_in[1];
    const float* W0 = (const float*)d_in[2];
    const float* b0 = (const float*)d_in[3];
    const float* W1 = (const float*)d_in[4];
    const float* b1 = (const float*)d_in[5];
    const float* W2 = (const float*)d_in[6];
    const float* b2 = (const float*)d_in[7];
    const float* W3 = (const float*)d_in[8];

    const int B = in_sizes[1] / 2;
    const int nchunks = (B + 15) / 16;

    int dev = 0, sms = 148;
    cudaGetDevice(&dev);
    cudaDeviceGetAttribute(&sms, cudaDevAttrMultiProcessorCount, dev);
    int grid = (nchunks + NW - 1) / NW;
    if (grid > sms) grid = sms;

    cudaFuncSetAttribute(lnn_mma, cudaFuncAttributeMaxDynamicSharedMemorySize,
                         SMEM_BYTES);
    lnn_mma<<<grid, TPB, SMEM_BYTES>>>((const float2*)x, W0, b0, W1, b1,
                                       W2, b2, W3, (float2*)d_out, B, nchunks);
}